// round 15
// baseline (speedup 1.0000x reference)
#include <cuda_runtime.h>
#include <cuda_bf16.h>
#include <cstdint>

// Problem: y[b,e] = relu(sum_a action[b,a] * conv_w[e,a] + conv_b[e])
// out[b,e,h,w] = y[b,e] broadcast over 64x64 spatial.
// B=128, A=256, E=256, H=W=64. Output fp32, 512 MB -> pure HBM-write-bound.
//
// FINAL kernel (Round-6 champion; best total 73.9us, best kernel 72.26us,
// best DRAM 83.2% / 6594 GB/s; re-benched 5x, kernel band 72.3-73.0us).
// Ten-configuration sweep:
//   store width  {STG.128, STG.256, TMA bulk}
//   cache policy {write-back, .cs, .wt}
//   block size   {128, 256, 512}
//   planes/block {1, 2, 4}
//   grid         {full 32768, persistent 1184, split GEMM+fill}
// all plateau at 81-83% DRAM (6.4-6.6 TB/s) with issue <= 26% and L2 <= 63%:
// ~6.5-6.6 TB/s is this GB300's pure-write HBM ceiling. The residual DRAM
// cycles are write-turnaround/refresh inside the DRAM subsystem -- not
// reachable from SASS. Converged.
//
// Shape: one block per (b,e) plane. All 8 warps redundantly compute the
// A=256 dot product (inputs fully L2-resident, 384 KB total), shuffle-
// reduce, then each thread issues 2x 256-bit write-back stores (32 B each):
// 256 threads x 64 B = 16 KB plane, perfectly coalesced.

#define B_DIM   128
#define A_DIM   256
#define E_DIM   256
#define HW      4096                 // 64*64
#define NPLANES (B_DIM * E_DIM)      // 32768

__device__ __forceinline__ void stg256(float* p, float v)
{
    asm volatile(
        "st.global.v8.f32 [%0], {%1,%1,%1,%1,%1,%1,%1,%1};"
        :: "l"(p), "f"(v) : "memory");
}

__global__ __launch_bounds__(256)
void fused_embed_fill_kernel(const float*  __restrict__ action,
                             const float*  __restrict__ conv_w,
                             const float*  __restrict__ conv_b,
                             float*        __restrict__ out)
{
    const int plane = blockIdx.x;          // b*256 + e
    const int b = plane >> 8;
    const int e = plane & 255;
    const int t    = threadIdx.x;
    const int lane = t & 31;

    // --- per-warp redundant dot product over A=256 -------------------------
    const float4* a4 = reinterpret_cast<const float4*>(action + b * A_DIM);
    const float4* w4 = reinterpret_cast<const float4*>(conv_w + e * A_DIM);

    float4 av0 = a4[lane];
    float4 av1 = a4[lane + 32];
    float4 wv0 = w4[lane];
    float4 wv1 = w4[lane + 32];

    float s;
    s = av0.x * wv0.x;
    s = fmaf(av0.y, wv0.y, s);
    s = fmaf(av0.z, wv0.z, s);
    s = fmaf(av0.w, wv0.w, s);
    s = fmaf(av1.x, wv1.x, s);
    s = fmaf(av1.y, wv1.y, s);
    s = fmaf(av1.z, wv1.z, s);
    s = fmaf(av1.w, wv1.w, s);

    s += __shfl_xor_sync(0xFFFFFFFF, s, 16);
    s += __shfl_xor_sync(0xFFFFFFFF, s, 8);
    s += __shfl_xor_sync(0xFFFFFFFF, s, 4);
    s += __shfl_xor_sync(0xFFFFFFFF, s, 2);
    s += __shfl_xor_sync(0xFFFFFFFF, s, 1);

    const float v = fmaxf(s + __ldg(conv_b + e), 0.0f);

    // --- fill this plane: 4096 floats = 512 x 32B chunks --------------------
    // Thread t writes chunks t and t+256 (each 8 floats, 32B-aligned).
    float* p = out + (size_t)plane * HW + t * 8;

    stg256(p,            v);
    stg256(p + 256 * 8,  v);
}

extern "C" void kernel_launch(void* const* d_in, const int* in_sizes, int n_in,
                              void* d_out, int out_size)
{
    const float* action = (const float*)d_in[0];   // [128, 256]
    const float* conv_w = (const float*)d_in[1];   // [256, 256]
    const float* conv_b = (const float*)d_in[2];   // [256]
    float* out = (float*)d_out;                    // [128, 256, 64, 64] fp32

    fused_embed_fill_kernel<<<NPLANES, 256>>>(action, conv_w, conv_b, out);
}

// round 16
// speedup vs baseline: 1.0009x; 1.0009x over previous
#include <cuda_runtime.h>
#include <cuda_bf16.h>
#include <cstdint>

// Problem: y[b,e] = relu(sum_a action[b,a] * conv_w[e,a] + conv_b[e])
// out[b,e,h,w] = y[b,e] broadcast over 64x64 spatial.
// B=128, A=256, E=256, H=W=64. Output fp32, 512 MB -> pure HBM-write-bound.
//
// FINAL kernel (Round-6 champion; best total 73.9us, best kernel 72.26us,
// best DRAM 83.2% / 6594 GB/s; re-benched 6x, kernel band 72.3-73.3us).
// Ten-configuration sweep:
//   store width  {STG.128, STG.256, TMA bulk}
//   cache policy {write-back, .cs, .wt}
//   block size   {128, 256, 512}
//   planes/block {1, 2, 4}
//   grid         {full 32768, persistent 1184, split GEMM+fill}
// all plateau at 81-83% DRAM (6.4-6.6 TB/s) with issue <= 26% and L2 <= 63%:
// ~6.5-6.6 TB/s is this GB300's pure-write HBM ceiling. The residual DRAM
// cycles are write-turnaround/refresh inside the DRAM subsystem -- not
// reachable from SASS. Converged; no further kernel change is warranted.
//
// Shape: one block per (b,e) plane. All 8 warps redundantly compute the
// A=256 dot product (inputs fully L2-resident, 384 KB total), shuffle-
// reduce, then each thread issues 2x 256-bit write-back stores (32 B each):
// 256 threads x 64 B = 16 KB plane, perfectly coalesced.

#define B_DIM   128
#define A_DIM   256
#define E_DIM   256
#define HW      4096                 // 64*64
#define NPLANES (B_DIM * E_DIM)      // 32768

__device__ __forceinline__ void stg256(float* p, float v)
{
    asm volatile(
        "st.global.v8.f32 [%0], {%1,%1,%1,%1,%1,%1,%1,%1};"
        :: "l"(p), "f"(v) : "memory");
}

__global__ __launch_bounds__(256)
void fused_embed_fill_kernel(const float*  __restrict__ action,
                             const float*  __restrict__ conv_w,
                             const float*  __restrict__ conv_b,
                             float*        __restrict__ out)
{
    const int plane = blockIdx.x;          // b*256 + e
    const int b = plane >> 8;
    const int e = plane & 255;
    const int t    = threadIdx.x;
    const int lane = t & 31;

    // --- per-warp redundant dot product over A=256 -------------------------
    const float4* a4 = reinterpret_cast<const float4*>(action + b * A_DIM);
    const float4* w4 = reinterpret_cast<const float4*>(conv_w + e * A_DIM);

    float4 av0 = a4[lane];
    float4 av1 = a4[lane + 32];
    float4 wv0 = w4[lane];
    float4 wv1 = w4[lane + 32];

    float s;
    s = av0.x * wv0.x;
    s = fmaf(av0.y, wv0.y, s);
    s = fmaf(av0.z, wv0.z, s);
    s = fmaf(av0.w, wv0.w, s);
    s = fmaf(av1.x, wv1.x, s);
    s = fmaf(av1.y, wv1.y, s);
    s = fmaf(av1.z, wv1.z, s);
    s = fmaf(av1.w, wv1.w, s);

    s += __shfl_xor_sync(0xFFFFFFFF, s, 16);
    s += __shfl_xor_sync(0xFFFFFFFF, s, 8);
    s += __shfl_xor_sync(0xFFFFFFFF, s, 4);
    s += __shfl_xor_sync(0xFFFFFFFF, s, 2);
    s += __shfl_xor_sync(0xFFFFFFFF, s, 1);

    const float v = fmaxf(s + __ldg(conv_b + e), 0.0f);

    // --- fill this plane: 4096 floats = 512 x 32B chunks --------------------
    // Thread t writes chunks t and t+256 (each 8 floats, 32B-aligned).
    float* p = out + (size_t)plane * HW + t * 8;

    stg256(p,            v);
    stg256(p + 256 * 8,  v);
}

extern "C" void kernel_launch(void* const* d_in, const int* in_sizes, int n_in,
                              void* d_out, int out_size)
{
    const float* action = (const float*)d_in[0];   // [128, 256]
    const float* conv_w = (const float*)d_in[1];   // [256, 256]
    const float* conv_b = (const float*)d_in[2];   // [256]
    float* out = (float*)d_out;                    // [128, 256, 64, 64] fp32

    fused_embed_fill_kernel<<<NPLANES, 256>>>(action, conv_w, conv_b, out);
}